// round 8
// baseline (speedup 1.0000x reference)
#include <cuda_runtime.h>
#include <cuda_fp16.h>
#include <cstdint>

#define NUM_EXPERT 16
#define IN_FEAT 1024
#define OUT_FEAT 1024
#define BATCH 8192

#define BM 128
#define BN 256
#define BK 32
#define NCHUNK (IN_FEAT / BK)    // 32
#define THREADS 256
#define SPAD 40                  // fp16 per smem row (32 data + 8 pad)
#define ROWB (SPAD * 2)          // 80 B per row
#define OFF_A 0
#define OFF_W (BM * ROWB)        // 10240
#define STAGE_SZ ((BM + BN) * ROWB)   // 30720
#define NSTAGE 3
#define SMEM_TILES 512
#define SMEM_TOTAL (SMEM_TILES + NSTAGE * STAGE_SZ)   // 92672

#define WBLOCKS (NUM_EXPERT * OUT_FEAT * IN_FEAT / 8 / 256)   // 8192 (2 float4/thread)
#define ABLOCKS (BATCH * IN_FEAT / 4 / 256)                   // 2048

__device__ int g_counts[NUM_EXPERT];
__device__ int g_rows[NUM_EXPERT * BATCH];
__device__ __align__(16) unsigned short g_whi[NUM_EXPERT * OUT_FEAT * IN_FEAT]; // 33.5 MB
__device__ __align__(16) unsigned short g_ahi[BATCH * IN_FEAT];                 // 16.8 MB

// ---------------- helpers ----------------
__device__ __forceinline__ uint32_t smem_u32(const void* p) {
    uint32_t a;
    asm("{ .reg .u64 t; cvta.to.shared.u64 t, %1; cvt.u32.u64 %0, t; }" : "=r"(a) : "l"(p));
    return a;
}
__device__ __forceinline__ uint32_t pack_h2(float x, float y) {
    uint32_t r;
    asm("cvt.rn.f16x2.f32 %0, %1, %2;" : "=r"(r) : "f"(y), "f"(x));
    return r;
}
__device__ __forceinline__ void cp16(uint32_t dst, const void* src, uint32_t bytes) {
    asm volatile("cp.async.cg.shared.global [%0], [%1], 16, %2;"
                 :: "r"(dst), "l"(src), "r"(bytes) : "memory");
}
__device__ __forceinline__ void cp_commit() {
    asm volatile("cp.async.commit_group;" ::: "memory");
}
template <int N>
__device__ __forceinline__ void cp_wait() {
    asm volatile("cp.async.wait_group %0;" :: "n"(N) : "memory");
}
__device__ __forceinline__ void ldsm4(uint32_t* r, uint32_t addr) {
    asm volatile("ldmatrix.sync.aligned.m8n8.x4.shared.b16 {%0,%1,%2,%3}, [%4];"
                 : "=r"(r[0]), "=r"(r[1]), "=r"(r[2]), "=r"(r[3]) : "r"(addr));
}
__device__ __forceinline__ void mma16816(float* d, const uint32_t* a, const uint32_t* b) {
    asm volatile(
        "mma.sync.aligned.m16n8k16.row.col.f32.f16.f16.f32 "
        "{%0,%1,%2,%3}, {%4,%5,%6,%7}, {%8,%9}, {%0,%1,%2,%3};"
        : "+f"(d[0]), "+f"(d[1]), "+f"(d[2]), "+f"(d[3])
        : "r"(a[0]), "r"(a[1]), "r"(a[2]), "r"(a[3]), "r"(b[0]), "r"(b[1]));
}

// ---------------- fused conversion prepass (counts pre-zeroed by memset) ----------------
__global__ __launch_bounds__(256)
void convert_all_kernel(const float* __restrict__ w,
                        const float* __restrict__ a,
                        const int* __restrict__ gate) {
    if (blockIdx.x < WBLOCKS) {
        int i = (blockIdx.x * 256 + threadIdx.x) * 2;
        #pragma unroll
        for (int q = 0; q < 2; q++) {
            float4 v = reinterpret_cast<const float4*>(w)[i + q];
            reinterpret_cast<uint2*>(g_whi)[i + q] =
                make_uint2(pack_h2(v.x, v.y), pack_h2(v.z, v.w));
        }
    } else {
        int j = (blockIdx.x - WBLOCKS) * 256 + threadIdx.x;   // one float4 of A
        if (j < BATCH) {
            int e = gate[j];
            int pos = atomicAdd(&g_counts[e], 1);
            g_rows[e * BATCH + pos] = j;
        }
        float4 v = reinterpret_cast<const float4*>(a)[j];
        reinterpret_cast<uint2*>(g_ahi)[j] =
            make_uint2(pack_h2(v.x, v.y), pack_h2(v.z, v.w));
    }
}

// ---------------- grouped GEMM (fp16 single-pass, 128x256 CTA, 1 barrier/chunk) --------
__global__ __launch_bounds__(THREADS, 1)
void moe_mma_kernel(float* __restrict__ out) {
    const int e = blockIdx.z;
    const int cnt = g_counts[e];
    const int row0 = blockIdx.y * BM;
    if (row0 >= cnt) return;
    const int col0 = blockIdx.x * BN;

    extern __shared__ char smem[];
    int* srows = (int*)smem;

    const int tid = threadIdx.x;
    const int wid = tid >> 5;
    const int lane = tid & 31;
    const int warp_m = wid >> 2;      // 0..1 -> 64-row half
    const int warp_n = wid & 3;       // 0..3 -> 64-col quarter

    if (tid < BM) {
        int r = row0 + tid;
        srows[tid] = (r < cnt) ? g_rows[e * BATCH + r] : -1;
    }
    __syncthreads();

    const uint32_t TILES = smem_u32(smem) + SMEM_TILES;

    // ---- cp.async assignments: A 2 chunks/thread, W 4 chunks/thread (16B each)
    const unsigned short* a_p[2];
    uint32_t a_dst[2], abytes[2];
    #pragma unroll
    for (int i = 0; i < 2; i++) {
        int idx = tid + i * THREADS;   // 0..511
        int m  = idx >> 2;
        int kq = idx & 3;
        a_dst[i] = (uint32_t)(m * ROWB + kq * 16);
        int r = srows[m];
        abytes[i] = (r >= 0) ? 16u : 0u;
        a_p[i] = g_ahi + (size_t)(r < 0 ? 0 : r) * IN_FEAT + kq * 8;
    }
    const unsigned short* w_p[4];
    uint32_t w_dst[4];
    #pragma unroll
    for (int i = 0; i < 4; i++) {
        int idx = tid + i * THREADS;   // 0..1023
        int n  = idx >> 2;
        int kq = idx & 3;
        w_dst[i] = (uint32_t)(n * ROWB + kq * 16);
        w_p[i] = g_whi + ((size_t)e * OUT_FEAT + col0 + n) * IN_FEAT + kq * 8;
    }

    // ---- ldmatrix per-lane offsets (bytes within a tile)
    const int arow  = lane & 15;
    const int akoff = (lane >> 4) << 3;
    const uint32_t a_off = (uint32_t)((warp_m * 64 + arow) * SPAD + akoff) * 2;
    const int brow  = ((lane >> 4) << 3) + (lane & 7);
    const int bkoff = ((lane >> 3) & 1) << 3;
    const uint32_t b_off = (uint32_t)((warp_n * 64 + brow) * SPAD + bkoff) * 2;

    float acc[4][8][4];
    #pragma unroll
    for (int mt = 0; mt < 4; mt++)
        #pragma unroll
        for (int nt = 0; nt < 8; nt++)
            #pragma unroll
            for (int q = 0; q < 4; q++) acc[mt][nt][q] = 0.0f;

    // ---- prologue: prefetch chunks 0..NSTAGE-2
    #pragma unroll
    for (int s = 0; s < NSTAGE - 1; s++) {
        uint32_t base = TILES + s * STAGE_SZ;
        #pragma unroll
        for (int i = 0; i < 2; i++)
            cp16(base + OFF_A + a_dst[i], a_p[i] + s * BK, abytes[i]);
        #pragma unroll
        for (int i = 0; i < 4; i++)
            cp16(base + OFF_W + w_dst[i], w_p[i] + s * BK, 16u);
        cp_commit();
    }

    #pragma unroll 1
    for (int c = 0; c < NCHUNK; c++) {
        cp_wait<NSTAGE - 2>();      // chunk c landed
        __syncthreads();            // also: all warps done reading stage (c-1)

        // issue loads for chunk c+NSTAGE-1 into the stage freed last iteration
        const int cn = c + NSTAGE - 1;
        if (cn < NCHUNK) {
            uint32_t base = TILES + (uint32_t)(cn % NSTAGE) * STAGE_SZ;
            #pragma unroll
            for (int i = 0; i < 2; i++)
                cp16(base + OFF_A + a_dst[i], a_p[i] + cn * BK, abytes[i]);
            #pragma unroll
            for (int i = 0; i < 4; i++)
                cp16(base + OFF_W + w_dst[i], w_p[i] + cn * BK, 16u);
        }
        cp_commit();                // unconditional: uniform group counting

        // compute chunk c
        const uint32_t soff = TILES + (uint32_t)(c % NSTAGE) * STAGE_SZ;
        #pragma unroll
        for (int ks = 0; ks < 2; ks++) {
            uint32_t w_[4][4];
            #pragma unroll
            for (int ng = 0; ng < 4; ng++)
                ldsm4(w_[ng], soff + OFF_W + b_off + ks * 32 + ng * (16 * ROWB));
            #pragma unroll
            for (int mt = 0; mt < 4; mt++) {
                uint32_t a_[4];
                ldsm4(a_, soff + OFF_A + a_off + ks * 32 + mt * (16 * ROWB));
                #pragma unroll
                for (int nt = 0; nt < 8; nt++)
                    mma16816(acc[mt][nt], a_, &w_[nt >> 1][(nt & 1) * 2]);
            }
        }
    }

    // ---- epilogue: scatter accumulators to out
    const int rbase = warp_m * 64 + (lane >> 2);
    const int cbase = col0 + warp_n * 64 + (lane & 3) * 2;
    #pragma unroll
    for (int mt = 0; mt < 4; mt++) {
        int r0 = srows[rbase + mt * 16];
        int r1 = srows[rbase + mt * 16 + 8];
        #pragma unroll
        for (int nt = 0; nt < 8; nt++) {
            int col = cbase + nt * 8;
            if (r0 >= 0)
                *reinterpret_cast<float2*>(out + (size_t)r0 * OUT_FEAT + col) =
                    make_float2(acc[mt][nt][0], acc[mt][nt][1]);
            if (r1 >= 0)
                *reinterpret_cast<float2*>(out + (size_t)r1 * OUT_FEAT + col) =
                    make_float2(acc[mt][nt][2], acc[mt][nt][3]);
        }
    }
}

extern "C" void kernel_launch(void* const* d_in, const int* in_sizes, int n_in,
                              void* d_out, int out_size) {
    const float* inp    = (const float*)d_in[0];   // [8192, 1024] f32
    const int*   gate   = (const int*)d_in[1];     // [8192] i32
    const float* weight = (const float*)d_in[2];   // [16, 1024, 1024] f32
    float* out = (float*)d_out;                    // [8192, 1024] f32

    cudaFuncSetAttribute(moe_mma_kernel, cudaFuncAttributeMaxDynamicSharedMemorySize,
                         SMEM_TOTAL);

    void* counts_ptr = nullptr;
    cudaGetSymbolAddress(&counts_ptr, g_counts);
    cudaMemsetAsync(counts_ptr, 0, NUM_EXPERT * sizeof(int));

    convert_all_kernel<<<WBLOCKS + ABLOCKS, 256>>>(weight, inp, gate);

    dim3 grid(OUT_FEAT / BN, BATCH / BM, NUM_EXPERT);
    moe_mma_kernel<<<grid, THREADS, SMEM_TOTAL>>>(out);
}

// round 9
// speedup vs baseline: 1.1715x; 1.1715x over previous
#include <cuda_runtime.h>
#include <cuda_fp16.h>
#include <cstdint>

#define NUM_EXPERT 16
#define IN_FEAT 1024
#define OUT_FEAT 1024
#define BATCH 8192

#define BM 128
#define BN 128
#define BK 32
#define NCHUNK (IN_FEAT / BK)    // 32
#define THREADS 256
#define SPAD 40                  // fp16 per smem row (32 data + 8 pad)
#define ROWB (SPAD * 2)          // 80 B
#define OFF_A 0
#define OFF_W (BM * ROWB)        // 10240
#define STAGE_SZ ((BM + BN) * ROWB)   // 20480
#define NSTAGE 4
#define SMEM_TILES 512
#define SMEM_TOTAL (SMEM_TILES + NSTAGE * STAGE_SZ)   // 82432

#define MAX_TILES 79             // Sum ceil(cnt_e/128) <= 64 + 15
#define WBLOCKS (NUM_EXPERT * OUT_FEAT * IN_FEAT / 8 / 256)   // 8192
#define ABLOCKS (BATCH * IN_FEAT / 8 / 256)                   // 1024

__device__ int g_counts[NUM_EXPERT];
__device__ int g_rows[NUM_EXPERT * BATCH];
__device__ int g_tiles[MAX_TILES];   // (e << 16) | row_tile
__device__ int g_ntiles;
__device__ __align__(16) unsigned short g_whi[NUM_EXPERT * OUT_FEAT * IN_FEAT]; // 33.5 MB
__device__ __align__(16) unsigned short g_ahi[BATCH * IN_FEAT];                 // 16.8 MB

// ---------------- helpers ----------------
__device__ __forceinline__ uint32_t smem_u32(const void* p) {
    uint32_t a;
    asm("{ .reg .u64 t; cvta.to.shared.u64 t, %1; cvt.u32.u64 %0, t; }" : "=r"(a) : "l"(p));
    return a;
}
__device__ __forceinline__ uint32_t pack_h2(float x, float y) {
    uint32_t r;
    asm("cvt.rn.f16x2.f32 %0, %1, %2;" : "=r"(r) : "f"(y), "f"(x));
    return r;
}
__device__ __forceinline__ void cp16(uint32_t dst, const void* src, uint32_t bytes) {
    asm volatile("cp.async.cg.shared.global [%0], [%1], 16, %2;"
                 :: "r"(dst), "l"(src), "r"(bytes) : "memory");
}
__device__ __forceinline__ void cp_commit() {
    asm volatile("cp.async.commit_group;" ::: "memory");
}
template <int N>
__device__ __forceinline__ void cp_wait() {
    asm volatile("cp.async.wait_group %0;" :: "n"(N) : "memory");
}
__device__ __forceinline__ void ldsm4(uint32_t* r, uint32_t addr) {
    asm volatile("ldmatrix.sync.aligned.m8n8.x4.shared.b16 {%0,%1,%2,%3}, [%4];"
                 : "=r"(r[0]), "=r"(r[1]), "=r"(r[2]), "=r"(r[3]) : "r"(addr));
}
__device__ __forceinline__ void mma16816(float* d, const uint32_t* a, const uint32_t* b) {
    asm volatile(
        "mma.sync.aligned.m16n8k16.row.col.f32.f16.f16.f32 "
        "{%0,%1,%2,%3}, {%4,%5,%6,%7}, {%8,%9}, {%0,%1,%2,%3};"
        : "+f"(d[0]), "+f"(d[1]), "+f"(d[2]), "+f"(d[3])
        : "r"(a[0]), "r"(a[1]), "r"(a[2]), "r"(a[3]), "r"(b[0]), "r"(b[1]));
}

// ---------------- routing ----------------
__global__ void scatter_kernel(const int* __restrict__ gate) {
    int t = blockIdx.x * blockDim.x + threadIdx.x;
    if (t < BATCH) {
        int e = gate[t];
        int pos = atomicAdd(&g_counts[e], 1);
        g_rows[e * BATCH + pos] = t;
    }
}

// ---------------- conversion + worklist build ----------------
__global__ __launch_bounds__(256)
void convert_all_kernel(const float* __restrict__ w, const float* __restrict__ a) {
    if (blockIdx.x < WBLOCKS) {
        int i = (blockIdx.x * 256 + threadIdx.x) * 2;
        #pragma unroll
        for (int q = 0; q < 2; q++) {
            float4 v = reinterpret_cast<const float4*>(w)[i + q];
            reinterpret_cast<uint2*>(g_whi)[i + q] =
                make_uint2(pack_h2(v.x, v.y), pack_h2(v.z, v.w));
        }
    } else if (blockIdx.x < WBLOCKS + ABLOCKS) {
        int i = ((blockIdx.x - WBLOCKS) * 256 + threadIdx.x) * 2;
        #pragma unroll
        for (int q = 0; q < 2; q++) {
            float4 v = reinterpret_cast<const float4*>(a)[i + q];
            reinterpret_cast<uint2*>(g_ahi)[i + q] =
                make_uint2(pack_h2(v.x, v.y), pack_h2(v.z, v.w));
        }
    } else if (threadIdx.x == 0) {
        // counts are final (written by the previous launch)
        int n = 0;
        #pragma unroll
        for (int e = 0; e < NUM_EXPERT; e++) {
            int nt = (g_counts[e] + BM - 1) / BM;
            for (int t = 0; t < nt; t++) g_tiles[n++] = (e << 16) | t;
        }
        g_ntiles = n;
    }
}

// ---------------- grouped GEMM (fp16, 128x128 CTA, balanced worklist) ----------------
__global__ __launch_bounds__(THREADS, 2)
void moe_mma_kernel(float* __restrict__ out) {
    const int ty = blockIdx.y;
    if (ty >= g_ntiles) return;
    const int item = g_tiles[ty];
    const int e = item >> 16;
    const int row0 = (item & 0xFFFF) * BM;
    const int cnt = g_counts[e];
    const int col0 = blockIdx.x * BN;

    extern __shared__ char smem[];
    int* srows = (int*)smem;

    const int tid = threadIdx.x;
    const int wid = tid >> 5;
    const int lane = tid & 31;
    const int warp_m = wid >> 2;      // 0..1 -> 64-row half
    const int warp_n = wid & 3;       // 0..3 -> 32-col quarter

    if (tid < BM) {
        int r = row0 + tid;
        srows[tid] = (r < cnt) ? g_rows[e * BATCH + r] : -1;
    }
    __syncthreads();

    const uint32_t TILES = smem_u32(smem) + SMEM_TILES;

    // ---- cp.async assignments: 2 x (A, W) 16B chunks per K-chunk per thread
    const unsigned short* a_p[2];
    const unsigned short* w_p[2];
    uint32_t dst_off[2], abytes[2];
    #pragma unroll
    for (int i = 0; i < 2; i++) {
        int idx = tid + i * THREADS;   // 0..511
        int m  = idx >> 2;
        int kq = idx & 3;
        dst_off[i] = (uint32_t)(m * ROWB + kq * 16);
        int r = srows[m];
        abytes[i] = (r >= 0) ? 16u : 0u;
        a_p[i] = g_ahi + (size_t)(r < 0 ? 0 : r) * IN_FEAT + kq * 8;
        w_p[i] = g_whi + ((size_t)e * OUT_FEAT + col0 + m) * IN_FEAT + kq * 8;
    }

    // ---- ldmatrix per-lane offsets
    const int arow  = lane & 15;
    const int akoff = (lane >> 4) << 3;
    const uint32_t a_off = (uint32_t)((warp_m * 64 + arow) * SPAD + akoff) * 2;
    const int brow  = ((lane >> 4) << 3) + (lane & 7);
    const int bkoff = ((lane >> 3) & 1) << 3;
    const uint32_t b_off = (uint32_t)((warp_n * 32 + brow) * SPAD + bkoff) * 2;

    float acc[4][4][4];
    #pragma unroll
    for (int mt = 0; mt < 4; mt++)
        #pragma unroll
        for (int nt = 0; nt < 4; nt++)
            #pragma unroll
            for (int q = 0; q < 4; q++) acc[mt][nt][q] = 0.0f;

    // ---- prologue: prefetch chunks 0..NSTAGE-2
    #pragma unroll
    for (int s = 0; s < NSTAGE - 1; s++) {
        uint32_t base = TILES + s * STAGE_SZ;
        #pragma unroll
        for (int i = 0; i < 2; i++) {
            cp16(base + OFF_A + dst_off[i], a_p[i] + s * BK, abytes[i]);
            cp16(base + OFF_W + dst_off[i], w_p[i] + s * BK, 16u);
        }
        cp_commit();
    }

    #pragma unroll 1
    for (int c = 0; c < NCHUNK; c++) {
        cp_wait<NSTAGE - 2>();      // chunk c landed
        __syncthreads();            // all warps done reading the stage we refill

        const int cn = c + NSTAGE - 1;
        if (cn < NCHUNK) {
            uint32_t base = TILES + (uint32_t)(cn % NSTAGE) * STAGE_SZ;
            #pragma unroll
            for (int i = 0; i < 2; i++) {
                cp16(base + OFF_A + dst_off[i], a_p[i] + cn * BK, abytes[i]);
                cp16(base + OFF_W + dst_off[i], w_p[i] + cn * BK, 16u);
            }
        }
        cp_commit();                // uniform group counting

        const uint32_t soff = TILES + (uint32_t)(c % NSTAGE) * STAGE_SZ;
        #pragma unroll
        for (int ks = 0; ks < 2; ks++) {
            uint32_t w_[2][4];
            ldsm4(w_[0], soff + OFF_W + b_off + ks * 32);
            ldsm4(w_[1], soff + OFF_W + b_off + ks * 32 + 16 * ROWB);
            #pragma unroll
            for (int mt = 0; mt < 4; mt++) {
                uint32_t a_[4];
                ldsm4(a_, soff + OFF_A + a_off + ks * 32 + mt * (16 * ROWB));
                #pragma unroll
                for (int nt = 0; nt < 4; nt++)
                    mma16816(acc[mt][nt], a_, &w_[nt >> 1][(nt & 1) * 2]);
            }
        }
    }

    // ---- epilogue
    const int rbase = warp_m * 64 + (lane >> 2);
    const int cbase = col0 + warp_n * 32 + (lane & 3) * 2;
    #pragma unroll
    for (int mt = 0; mt < 4; mt++) {
        int r0 = srows[rbase + mt * 16];
        int r1 = srows[rbase + mt * 16 + 8];
        #pragma unroll
        for (int nt = 0; nt < 4; nt++) {
            int col = cbase + nt * 8;
            if (r0 >= 0)
                *reinterpret_cast<float2*>(out + (size_t)r0 * OUT_FEAT + col) =
                    make_float2(acc[mt][nt][0], acc[mt][nt][1]);
            if (r1 >= 0)
                *reinterpret_cast<float2*>(out + (size_t)r1 * OUT_FEAT + col) =
                    make_float2(acc[mt][nt][2], acc[mt][nt][3]);
        }
    }
}

extern "C" void kernel_launch(void* const* d_in, const int* in_sizes, int n_in,
                              void* d_out, int out_size) {
    const float* inp    = (const float*)d_in[0];   // [8192, 1024] f32
    const int*   gate   = (const int*)d_in[1];     // [8192] i32
    const float* weight = (const float*)d_in[2];   // [16, 1024, 1024] f32
    float* out = (float*)d_out;                    // [8192, 1024] f32

    cudaFuncSetAttribute(moe_mma_kernel, cudaFuncAttributeMaxDynamicSharedMemorySize,
                         SMEM_TOTAL);

    void* counts_ptr = nullptr;
    cudaGetSymbolAddress(&counts_ptr, g_counts);
    cudaMemsetAsync(counts_ptr, 0, NUM_EXPERT * sizeof(int));

    scatter_kernel<<<(BATCH + 255) / 256, 256>>>(gate);
    convert_all_kernel<<<WBLOCKS + ABLOCKS + 1, 256>>>(weight, inp);

    dim3 grid(OUT_FEAT / BN, MAX_TILES, 1);
    moe_mma_kernel<<<grid, THREADS, SMEM_TOTAL>>>(out);
}

// round 10
// speedup vs baseline: 1.1801x; 1.0073x over previous
#include <cuda_runtime.h>
#include <cuda_fp16.h>
#include <cstdint>

#define NUM_EXPERT 16
#define IN_FEAT 1024
#define OUT_FEAT 1024
#define BATCH 8192

#define BM 128
#define BN 128
#define BK 32
#define NCHUNK (IN_FEAT / BK)    // 32
#define THREADS 128              // 4 warps, warp tile 64x64
#define SPAD 40                  // fp16 per smem row (32 data + 8 pad)
#define ROWB (SPAD * 2)          // 80 B
#define OFF_A 0
#define OFF_W (BM * ROWB)        // 10240
#define STAGE_SZ ((BM + BN) * ROWB)   // 20480
#define NSTAGE 3
#define SMEM_TILES 512
#define SMEM_TOTAL (SMEM_TILES + NSTAGE * STAGE_SZ)   // 61952

#define MAX_TILES 79
#define WBLOCKS (NUM_EXPERT * OUT_FEAT * IN_FEAT / 8 / 256)   // 8192
#define ABLOCKS (BATCH * IN_FEAT / 8 / 256)                   // 1024

__device__ int g_counts[NUM_EXPERT];
__device__ int g_rows[NUM_EXPERT * BATCH];
__device__ __align__(16) unsigned short g_whi[NUM_EXPERT * OUT_FEAT * IN_FEAT]; // 33.5 MB
__device__ __align__(16) unsigned short g_ahi[BATCH * IN_FEAT];                 // 16.8 MB

// ---------------- helpers ----------------
__device__ __forceinline__ uint32_t smem_u32(const void* p) {
    uint32_t a;
    asm("{ .reg .u64 t; cvta.to.shared.u64 t, %1; cvt.u32.u64 %0, t; }" : "=r"(a) : "l"(p));
    return a;
}
__device__ __forceinline__ uint32_t pack_h2(float x, float y) {
    uint32_t r;
    asm("cvt.rn.f16x2.f32 %0, %1, %2;" : "=r"(r) : "f"(y), "f"(x));
    return r;
}
__device__ __forceinline__ void cp16(uint32_t dst, const void* src, uint32_t bytes) {
    asm volatile("cp.async.cg.shared.global [%0], [%1], 16, %2;"
                 :: "r"(dst), "l"(src), "r"(bytes) : "memory");
}
__device__ __forceinline__ void cp_commit() {
    asm volatile("cp.async.commit_group;" ::: "memory");
}
template <int N>
__device__ __forceinline__ void cp_wait() {
    asm volatile("cp.async.wait_group %0;" :: "n"(N) : "memory");
}
__device__ __forceinline__ void ldsm4(uint32_t* r, uint32_t addr) {
    asm volatile("ldmatrix.sync.aligned.m8n8.x4.shared.b16 {%0,%1,%2,%3}, [%4];"
                 : "=r"(r[0]), "=r"(r[1]), "=r"(r[2]), "=r"(r[3]) : "r"(addr));
}
__device__ __forceinline__ void mma16816(float* d, const uint32_t* a, const uint32_t* b) {
    asm volatile(
        "mma.sync.aligned.m16n8k16.row.col.f32.f16.f16.f32 "
        "{%0,%1,%2,%3}, {%4,%5,%6,%7}, {%8,%9}, {%0,%1,%2,%3};"
        : "+f"(d[0]), "+f"(d[1]), "+f"(d[2]), "+f"(d[3])
        : "r"(a[0]), "r"(a[1]), "r"(a[2]), "r"(a[3]), "r"(b[0]), "r"(b[1]));
}

// ---------------- fused conversion + routing (counts pre-zeroed by memset) ----------
__global__ __launch_bounds__(256)
void convert_all_kernel(const float* __restrict__ w,
                        const float* __restrict__ a,
                        const int* __restrict__ gate) {
    if (blockIdx.x < WBLOCKS) {
        int i = (blockIdx.x * 256 + threadIdx.x) * 2;
        #pragma unroll
        for (int q = 0; q < 2; q++) {
            float4 v = reinterpret_cast<const float4*>(w)[i + q];
            reinterpret_cast<uint2*>(g_whi)[i + q] =
                make_uint2(pack_h2(v.x, v.y), pack_h2(v.z, v.w));
        }
    } else {
        int b = blockIdx.x - WBLOCKS;
        int j = b * 256 + threadIdx.x;
        if (j < BATCH) {
            int e = gate[j];
            int pos = atomicAdd(&g_counts[e], 1);
            g_rows[e * BATCH + pos] = j;
        }
        int i = j * 2;
        #pragma unroll
        for (int q = 0; q < 2; q++) {
            float4 v = reinterpret_cast<const float4*>(a)[i + q];
            reinterpret_cast<uint2*>(g_ahi)[i + q] =
                make_uint2(pack_h2(v.x, v.y), pack_h2(v.z, v.w));
        }
    }
}

// ---------------- grouped GEMM (fp16, 128x128 CTA, 4 warps, 64x64 warp tile) --------
__global__ __launch_bounds__(THREADS, 3)
void moe_mma_kernel(float* __restrict__ out) {
    // map blockIdx.y -> (expert, row tile) from counts
    const int ty = blockIdx.y;
    int e = -1, tt = 0, cnt = 0;
    {
        int n = 0;
        #pragma unroll
        for (int i = 0; i < NUM_EXPERT; i++) {
            int ci = g_counts[i];
            int nt = (ci + BM - 1) >> 7;
            if (e < 0 && ty < n + nt) { e = i; tt = ty - n; cnt = ci; }
            n += nt;
        }
    }
    if (e < 0) return;
    const int row0 = tt * BM;
    const int col0 = blockIdx.x * BN;

    extern __shared__ char smem[];
    int* srows = (int*)smem;

    const int tid = threadIdx.x;
    const int wid = tid >> 5;
    const int lane = tid & 31;
    const int warp_m = wid >> 1;      // 0..1 -> 64-row half
    const int warp_n = wid & 1;       // 0..1 -> 64-col half

    {   // all 128 threads: one row each
        int r = row0 + tid;
        srows[tid] = (r < cnt) ? g_rows[e * BATCH + r] : -1;
    }
    __syncthreads();

    const uint32_t TILES = smem_u32(smem) + SMEM_TILES;

    // ---- cp.async assignments (exploit regularity: kq fixed, rows step by 32)
    const int m0 = tid >> 2;           // 0..31
    const int kq = tid & 3;            // 16B quarter
    const uint32_t a_dst0 = (uint32_t)(m0 * ROWB + kq * 16);
    int srow4[4];
    #pragma unroll
    for (int i = 0; i < 4; i++) srow4[i] = srows[m0 + i * 32];
    const unsigned short* w_p0 =
        g_whi + ((size_t)e * OUT_FEAT + col0 + m0) * IN_FEAT + kq * 8;

    // ---- ldmatrix per-lane offsets
    const uint32_t a_off =
        (uint32_t)((warp_m * 64 + (lane & 15)) * SPAD + ((lane >> 4) << 3)) * 2;
    const int brow  = ((lane >> 4) << 3) + (lane & 7);
    const int bkoff = ((lane >> 3) & 1) << 3;
    const uint32_t b_off = (uint32_t)((warp_n * 64 + brow) * SPAD + bkoff) * 2;

    float acc[4][8][4];
    #pragma unroll
    for (int mt = 0; mt < 4; mt++)
        #pragma unroll
        for (int nt = 0; nt < 8; nt++)
            #pragma unroll
            for (int q = 0; q < 4; q++) acc[mt][nt][q] = 0.0f;

    // ---- prologue: prefetch chunks 0..NSTAGE-2
    #pragma unroll
    for (int s = 0; s < NSTAGE - 1; s++) {
        uint32_t base = TILES + s * STAGE_SZ;
        #pragma unroll
        for (int i = 0; i < 4; i++) {
            int r = srow4[i];
            const unsigned short* asrc =
                g_ahi + ((size_t)(r < 0 ? 0 : r) << 10) + kq * 8 + s * BK;
            cp16(base + OFF_A + a_dst0 + i * (32 * ROWB), asrc, (r >= 0) ? 16u : 0u);
            cp16(base + OFF_W + a_dst0 + i * (32 * ROWB),
                 w_p0 + (size_t)i * 32 * IN_FEAT + s * BK, 16u);
        }
        cp_commit();
    }

    #pragma unroll 1
    for (int c = 0; c < NCHUNK; c++) {
        cp_wait<NSTAGE - 2>();      // chunk c landed
        __syncthreads();            // all warps done reading the stage we refill

        const int cn = c + NSTAGE - 1;
        if (cn < NCHUNK) {
            uint32_t base = TILES + (uint32_t)(cn % NSTAGE) * STAGE_SZ;
            #pragma unroll
            for (int i = 0; i < 4; i++) {
                int r = srow4[i];
                const unsigned short* asrc =
                    g_ahi + ((size_t)(r < 0 ? 0 : r) << 10) + kq * 8 + cn * BK;
                cp16(base + OFF_A + a_dst0 + i * (32 * ROWB), asrc, (r >= 0) ? 16u : 0u);
                cp16(base + OFF_W + a_dst0 + i * (32 * ROWB),
                     w_p0 + (size_t)i * 32 * IN_FEAT + cn * BK, 16u);
            }
        }
        cp_commit();                // uniform group counting

        const uint32_t soff = TILES + (uint32_t)(c % NSTAGE) * STAGE_SZ;
        #pragma unroll
        for (int ks = 0; ks < 2; ks++) {
            uint32_t w_[4][4];
            #pragma unroll
            for (int ng = 0; ng < 4; ng++)
                ldsm4(w_[ng], soff + OFF_W + b_off + ks * 32 + ng * (16 * ROWB));
            #pragma unroll
            for (int mt = 0; mt < 4; mt++) {
                uint32_t a_[4];
                ldsm4(a_, soff + OFF_A + a_off + ks * 32 + mt * (16 * ROWB));
                #pragma unroll
                for (int nt = 0; nt < 8; nt++)
                    mma16816(acc[mt][nt], a_, &w_[nt >> 1][(nt & 1) * 2]);
            }
        }
    }

    // ---- epilogue
    const int rbase = warp_m * 64 + (lane >> 2);
    const int cbase = col0 + warp_n * 64 + (lane & 3) * 2;
    #pragma unroll
    for (int mt = 0; mt < 4; mt++) {
        int r0 = srows[rbase + mt * 16];
        int r1 = srows[rbase + mt * 16 + 8];
        #pragma unroll
        for (int nt = 0; nt < 8; nt++) {
            int col = cbase + nt * 8;
            if (r0 >= 0)
                *reinterpret_cast<float2*>(out + (size_t)r0 * OUT_FEAT + col) =
                    make_float2(acc[mt][nt][0], acc[mt][nt][1]);
            if (r1 >= 0)
                *reinterpret_cast<float2*>(out + (size_t)r1 * OUT_FEAT + col) =
                    make_float2(acc[mt][nt][2], acc[mt][nt][3]);
        }
    }
}

extern "C" void kernel_launch(void* const* d_in, const int* in_sizes, int n_in,
                              void* d_out, int out_size) {
    const float* inp    = (const float*)d_in[0];   // [8192, 1024] f32
    const int*   gate   = (const int*)d_in[1];     // [8192] i32
    const float* weight = (const float*)d_in[2];   // [16, 1024, 1024] f32
    float* out = (float*)d_out;                    // [8192, 1024] f32

    cudaFuncSetAttribute(moe_mma_kernel, cudaFuncAttributeMaxDynamicSharedMemorySize,
                         SMEM_TOTAL);

    void* counts_ptr = nullptr;
    cudaGetSymbolAddress(&counts_ptr, g_counts);
    cudaMemsetAsync(counts_ptr, 0, NUM_EXPERT * sizeof(int));

    convert_all_kernel<<<WBLOCKS + ABLOCKS, 256>>>(weight, inp, gate);

    dim3 grid(OUT_FEAT / BN, MAX_TILES, 1);
    moe_mma_kernel<<<grid, THREADS, SMEM_TOTAL>>>(out);
}

// round 11
// speedup vs baseline: 1.2954x; 1.0977x over previous
#include <cuda_runtime.h>
#include <cuda_fp16.h>
#include <cstdint>

#define NUM_EXPERT 16
#define IN_FEAT 1024
#define OUT_FEAT 1024
#define BATCH 8192

#define BM 128
#define BN 128
#define BK 32
#define NCHUNK (IN_FEAT / BK)    // 32
#define THREADS 256
#define SPAD 40                  // fp16 per A smem row (32 data + 8 pad)
#define ROWB (SPAD * 2)          // 80 B
#define ASTAGE (BM * ROWB)       // 10240
#define NSTAGE 4
#define SMEM_TILES 512
#define SMEM_TOTAL (SMEM_TILES + NSTAGE * ASTAGE)   // 41472

#define MAX_TILES 79
#define WBLOCKS (NUM_EXPERT * OUT_FEAT * IN_FEAT / 2 / 4 / 256)  // 8192 (1 uint4 dst/thread)
#define ABLOCKS (BATCH * IN_FEAT / 8 / 256)                      // 1024

__device__ int g_counts[NUM_EXPERT];
__device__ int g_rows[NUM_EXPERT * BATCH];
// W in HMMA B-fragment layout: [e][ntile(32)][chunk(32)][j(4)][lane(32)] uint4
__device__ uint4 g_wf[NUM_EXPERT * 32 * 32 * 128];               // 33.5 MB
__device__ __align__(16) unsigned short g_ahi[BATCH * IN_FEAT];  // 16.8 MB

// ---------------- helpers ----------------
__device__ __forceinline__ uint32_t smem_u32(const void* p) {
    uint32_t a;
    asm("{ .reg .u64 t; cvta.to.shared.u64 t, %1; cvt.u32.u64 %0, t; }" : "=r"(a) : "l"(p));
    return a;
}
__device__ __forceinline__ uint32_t pack_h2(float x, float y) {
    uint32_t r;
    asm("cvt.rn.f16x2.f32 %0, %1, %2;" : "=r"(r) : "f"(y), "f"(x));
    return r;
}
__device__ __forceinline__ void cp16(uint32_t dst, const void* src, uint32_t bytes) {
    asm volatile("cp.async.cg.shared.global [%0], [%1], 16, %2;"
                 :: "r"(dst), "l"(src), "r"(bytes) : "memory");
}
__device__ __forceinline__ void cp_commit() {
    asm volatile("cp.async.commit_group;" ::: "memory");
}
template <int N>
__device__ __forceinline__ void cp_wait() {
    asm volatile("cp.async.wait_group %0;" :: "n"(N) : "memory");
}
__device__ __forceinline__ void ldsm4(uint32_t* r, uint32_t addr) {
    asm volatile("ldmatrix.sync.aligned.m8n8.x4.shared.b16 {%0,%1,%2,%3}, [%4];"
                 : "=r"(r[0]), "=r"(r[1]), "=r"(r[2]), "=r"(r[3]) : "r"(addr));
}
__device__ __forceinline__ void mma16816(float* d, const uint32_t* a, const uint32_t* b) {
    asm volatile(
        "mma.sync.aligned.m16n8k16.row.col.f32.f16.f16.f32 "
        "{%0,%1,%2,%3}, {%4,%5,%6,%7}, {%8,%9}, {%0,%1,%2,%3};"
        : "+f"(d[0]), "+f"(d[1]), "+f"(d[2]), "+f"(d[3])
        : "r"(a[0]), "r"(a[1]), "r"(a[2]), "r"(a[3]), "r"(b[0]), "r"(b[1]));
}

// ---------------- fused prepass: W permute + A convert + routing ----------------
// Dst element mapping (uint4 index t, reg q, half h):
//   l = t&31, j = (t>>5)&3, c = (t>>7)&31, nt = (t>>12)&31, e = t>>17
//   ks = j>>1, ng = (j&1)*2 + (q>>1), r = q&1
//   n = nt*32 + ng*8 + (l>>2)
//   k = c*32 + ks*16 + r*8 + (l&3)*2 + h
__global__ __launch_bounds__(256)
void convert_all_kernel(const float* __restrict__ w,
                        const float* __restrict__ a,
                        const int* __restrict__ gate) {
    if (blockIdx.x < WBLOCKS) {
        int t = blockIdx.x * 256 + threadIdx.x;
        int l = t & 31, j = (t >> 5) & 3, c = (t >> 7) & 31;
        int nt = (t >> 12) & 31, e = t >> 17;
        int ks = j >> 1;
        int kbase = c * 32 + ks * 16 + (l & 3) * 2;
        uint4 d;
        uint32_t* dq = (uint32_t*)&d;
        #pragma unroll
        for (int q = 0; q < 4; q++) {
            int n = nt * 32 + ((j & 1) * 2 + (q >> 1)) * 8 + (l >> 2);
            int k = kbase + (q & 1) * 8;
            float2 v = *reinterpret_cast<const float2*>(
                w + (((size_t)e << 10) + n) * IN_FEAT + k);
            dq[q] = pack_h2(v.x, v.y);
        }
        g_wf[t] = d;
    } else {
        int b = blockIdx.x - WBLOCKS;
        int jj = b * 256 + threadIdx.x;
        if (jj < BATCH) {
            int e = gate[jj];
            int pos = atomicAdd(&g_counts[e], 1);
            g_rows[e * BATCH + pos] = jj;
        }
        int i = jj * 2;
        #pragma unroll
        for (int q = 0; q < 2; q++) {
            float4 v = reinterpret_cast<const float4*>(a)[i + q];
            reinterpret_cast<uint2*>(g_ahi)[i + q] =
                make_uint2(pack_h2(v.x, v.y), pack_h2(v.z, v.w));
        }
    }
}

// ---------------- grouped GEMM: A via smem/ldsm, W via direct LDG.128 ----------------
__global__ __launch_bounds__(THREADS, 2)
void moe_mma_kernel(float* __restrict__ out) {
    const int ty = blockIdx.y;
    int e = -1, tt = 0, cnt = 0;
    {
        int n = 0;
        #pragma unroll
        for (int i = 0; i < NUM_EXPERT; i++) {
            int ci = g_counts[i];
            int nti = (ci + BM - 1) >> 7;
            if (e < 0 && ty < n + nti) { e = i; tt = ty - n; cnt = ci; }
            n += nti;
        }
    }
    if (e < 0) return;
    const int row0 = tt * BM;
    const int col0 = blockIdx.x * BN;

    extern __shared__ char smem[];
    int* srows = (int*)smem;

    const int tid = threadIdx.x;
    const int wid = tid >> 5;
    const int lane = tid & 31;
    const int warp_m = wid >> 2;      // 0..1 -> 64-row half
    const int warp_n = wid & 3;       // 0..3 -> 32-col quarter

    if (tid < BM) {
        int r = row0 + tid;
        srows[tid] = (r < cnt) ? g_rows[e * BATCH + r] : -1;
    }
    __syncthreads();

    const uint32_t TILES = smem_u32(smem) + SMEM_TILES;

    // ---- A cp.async: 2 x 16B per thread per chunk
    const unsigned short* a_p[2];
    uint32_t a_dst[2], abytes[2];
    #pragma unroll
    for (int i = 0; i < 2; i++) {
        int idx = tid + i * THREADS;   // 0..511
        int m  = idx >> 2;
        int kq = idx & 3;
        a_dst[i] = (uint32_t)(m * ROWB + kq * 16);
        int r = srows[m];
        abytes[i] = (r >= 0) ? 16u : 0u;
        a_p[i] = g_ahi + ((size_t)(r < 0 ? 0 : r) << 10) + kq * 8;
    }

    // ---- W fragment pointer: per (e, global n-tile, chunk) 128 uint4
    const uint4* wq = g_wf +
        ((size_t)((e * 32 + blockIdx.x * 4 + warp_n) * 32)) * 128 + lane;

    // ---- A ldsm per-lane offset
    const uint32_t a_off =
        (uint32_t)((warp_m * 64 + (lane & 15)) * SPAD + ((lane >> 4) << 3)) * 2;

    float acc[4][4][4];
    #pragma unroll
    for (int mt = 0; mt < 4; mt++)
        #pragma unroll
        for (int nt = 0; nt < 4; nt++)
            #pragma unroll
            for (int q = 0; q < 4; q++) acc[mt][nt][q] = 0.0f;

    // ---- prologue: A stages 0..NSTAGE-2, W chunk 0
    #pragma unroll
    for (int s = 0; s < NSTAGE - 1; s++) {
        uint32_t base = TILES + s * ASTAGE;
        #pragma unroll
        for (int i = 0; i < 2; i++)
            cp16(base + a_dst[i], a_p[i] + s * BK, abytes[i]);
        cp_commit();
    }
    uint32_t wcur[16];
    #pragma unroll
    for (int j = 0; j < 4; j++) {
        uint4 t = __ldg(wq + j * 32);
        wcur[j * 4 + 0] = t.x; wcur[j * 4 + 1] = t.y;
        wcur[j * 4 + 2] = t.z; wcur[j * 4 + 3] = t.w;
    }

    #pragma unroll 1
    for (int c = 0; c < NCHUNK; c++) {
        cp_wait<NSTAGE - 2>();      // A chunk c landed
        __syncthreads();

        const int cn = c + NSTAGE - 1;
        if (cn < NCHUNK) {
            uint32_t base = TILES + (uint32_t)(cn % NSTAGE) * ASTAGE;
            #pragma unroll
            for (int i = 0; i < 2; i++)
                cp16(base + a_dst[i], a_p[i] + cn * BK, abytes[i]);
        }
        cp_commit();

        // prefetch W for chunk c+1
        uint32_t wnxt[16];
        if (c + 1 < NCHUNK) {
            #pragma unroll
            for (int j = 0; j < 4; j++) {
                uint4 t = __ldg(wq + (c + 1) * 128 + j * 32);
                wnxt[j * 4 + 0] = t.x; wnxt[j * 4 + 1] = t.y;
                wnxt[j * 4 + 2] = t.z; wnxt[j * 4 + 3] = t.w;
            }
        }

        const uint32_t soff = TILES + (uint32_t)(c % NSTAGE) * ASTAGE;
        #pragma unroll
        for (int ks = 0; ks < 2; ks++) {
            #pragma unroll
            for (int mt = 0; mt < 4; mt++) {
                uint32_t a_[4];
                ldsm4(a_, soff + a_off + ks * 32 + mt * (16 * ROWB));
                #pragma unroll
                for (int nt = 0; nt < 4; nt++)
                    mma16816(acc[mt][nt], a_,
                             &wcur[(ks * 2 + (nt >> 1)) * 4 + (nt & 1) * 2]);
            }
        }
        if (c + 1 < NCHUNK) {
            #pragma unroll
            for (int i = 0; i < 16; i++) wcur[i] = wnxt[i];
        }
    }

    // ---- epilogue
    const int rbase = warp_m * 64 + (lane >> 2);
    const int cbase = col0 + warp_n * 32 + (lane & 3) * 2;
    #pragma unroll
    for (int mt = 0; mt < 4; mt++) {
        int r0 = srows[rbase + mt * 16];
        int r1 = srows[rbase + mt * 16 + 8];
        #pragma unroll
        for (int nt = 0; nt < 4; nt++) {
            int col = cbase + nt * 8;
            if (r0 >= 0)
                *reinterpret_cast<float2*>(out + (size_t)r0 * OUT_FEAT + col) =
                    make_float2(acc[mt][nt][0], acc[mt][nt][1]);
            if (r1 >= 0)
                *reinterpret_cast<float2*>(out + (size_t)r1 * OUT_FEAT + col) =
                    make_float2(acc[mt][nt][2], acc[mt][nt][3]);
        }
    }
}

extern "C" void kernel_launch(void* const* d_in, const int* in_sizes, int n_in,
                              void* d_out, int out_size) {
    const float* inp    = (const float*)d_in[0];   // [8192, 1024] f32
    const int*   gate   = (const int*)d_in[1];     // [8192] i32
    const float* weight = (const float*)d_in[2];   // [16, 1024, 1024] f32
    float* out = (float*)d_out;                    // [8192, 1024] f32

    cudaFuncSetAttribute(moe_mma_kernel, cudaFuncAttributeMaxDynamicSharedMemorySize,
                         SMEM_TOTAL);

    void* counts_ptr = nullptr;
    cudaGetSymbolAddress(&counts_ptr, g_counts);
    cudaMemsetAsync(counts_ptr, 0, NUM_EXPERT * sizeof(int));

    convert_all_kernel<<<WBLOCKS + ABLOCKS, 256>>>(weight, inp, gate);

    dim3 grid(OUT_FEAT / BN, MAX_TILES, 1);
    moe_mma_kernel<<<grid, THREADS, SMEM_TOTAL>>>(out);
}

// round 12
// speedup vs baseline: 1.3337x; 1.0296x over previous
#include <cuda_runtime.h>
#include <cuda_fp16.h>
#include <cstdint>

#define NUM_EXPERT 16
#define IN_FEAT 1024
#define OUT_FEAT 1024
#define BATCH 8192

#define BM 128
#define BN 128
#define BK 64
#define NCHUNK (IN_FEAT / BK)    // 16
#define THREADS 256
#define SPAD 72                  // fp16 per A smem row (64 data + 8 pad)
#define ROWB (SPAD * 2)          // 144 B
#define ASTAGE (BM * ROWB)       // 18432
#define NSTAGE 3
#define SMEM_TILES 512
#define SMEM_TOTAL (SMEM_TILES + NSTAGE * ASTAGE)   // 55808

#define MAX_TILES 79
#define WBLOCKS (NUM_EXPERT * OUT_FEAT * IN_FEAT / 2 / 4 / 256)  // 8192
#define ABLOCKS (BATCH * IN_FEAT / 8 / 256)                      // 1024

__device__ int g_counts[NUM_EXPERT];
__device__ int g_rows[NUM_EXPERT * BATCH];
// W in HMMA B-fragment layout: [e][ntile(32)][half32k(32)][j(4)][lane(32)] uint4
__device__ uint4 g_wf[NUM_EXPERT * 32 * 32 * 128];               // 33.5 MB
__device__ __align__(16) unsigned short g_ahi[BATCH * IN_FEAT];  // 16.8 MB

// ---------------- helpers ----------------
__device__ __forceinline__ uint32_t smem_u32(const void* p) {
    uint32_t a;
    asm("{ .reg .u64 t; cvta.to.shared.u64 t, %1; cvt.u32.u64 %0, t; }" : "=r"(a) : "l"(p));
    return a;
}
__device__ __forceinline__ uint32_t pack_h2(float x, float y) {
    uint32_t r;
    asm("cvt.rn.f16x2.f32 %0, %1, %2;" : "=r"(r) : "f"(y), "f"(x));
    return r;
}
__device__ __forceinline__ void cp16(uint32_t dst, const void* src, uint32_t bytes) {
    asm volatile("cp.async.cg.shared.global [%0], [%1], 16, %2;"
                 :: "r"(dst), "l"(src), "r"(bytes) : "memory");
}
__device__ __forceinline__ void cp_commit() {
    asm volatile("cp.async.commit_group;" ::: "memory");
}
template <int N>
__device__ __forceinline__ void cp_wait() {
    asm volatile("cp.async.wait_group %0;" :: "n"(N) : "memory");
}
__device__ __forceinline__ void ldsm4(uint32_t* r, uint32_t addr) {
    asm volatile("ldmatrix.sync.aligned.m8n8.x4.shared.b16 {%0,%1,%2,%3}, [%4];"
                 : "=r"(r[0]), "=r"(r[1]), "=r"(r[2]), "=r"(r[3]) : "r"(addr));
}
__device__ __forceinline__ void mma16816(float* d, const uint32_t* a, const uint32_t* b) {
    asm volatile(
        "mma.sync.aligned.m16n8k16.row.col.f32.f16.f16.f32 "
        "{%0,%1,%2,%3}, {%4,%5,%6,%7}, {%8,%9}, {%0,%1,%2,%3};"
        : "+f"(d[0]), "+f"(d[1]), "+f"(d[2]), "+f"(d[3])
        : "r"(a[0]), "r"(a[1]), "r"(a[2]), "r"(a[3]), "r"(b[0]), "r"(b[1]));
}

// ---------------- fused prepass: W permute + A convert + routing ----------------
__global__ __launch_bounds__(256)
void convert_all_kernel(const float* __restrict__ w,
                        const float* __restrict__ a,
                        const int* __restrict__ gate) {
    if (blockIdx.x < WBLOCKS) {
        int t = blockIdx.x * 256 + threadIdx.x;
        int l = t & 31, j = (t >> 5) & 3, c = (t >> 7) & 31;
        int nt = (t >> 12) & 31, e = t >> 17;
        int ks = j >> 1;
        int kbase = c * 32 + ks * 16 + (l & 3) * 2;
        uint4 d;
        uint32_t* dq = (uint32_t*)&d;
        #pragma unroll
        for (int q = 0; q < 4; q++) {
            int n = nt * 32 + ((j & 1) * 2 + (q >> 1)) * 8 + (l >> 2);
            int k = kbase + (q & 1) * 8;
            float2 v = *reinterpret_cast<const float2*>(
                w + (((size_t)e << 10) + n) * IN_FEAT + k);
            dq[q] = pack_h2(v.x, v.y);
        }
        g_wf[t] = d;
    } else {
        int b = blockIdx.x - WBLOCKS;
        int jj = b * 256 + threadIdx.x;
        if (jj < BATCH) {
            int e = gate[jj];
            int pos = atomicAdd(&g_counts[e], 1);
            g_rows[e * BATCH + pos] = jj;
        }
        int i = jj * 2;
        #pragma unroll
        for (int q = 0; q < 2; q++) {
            float4 v = reinterpret_cast<const float4*>(a)[i + q];
            reinterpret_cast<uint2*>(g_ahi)[i + q] =
                make_uint2(pack_h2(v.x, v.y), pack_h2(v.z, v.w));
        }
    }
}

// ---------------- grouped GEMM: BK=64, W fragments via LDG, static double buffer ----
__global__ __launch_bounds__(THREADS, 2)
void moe_mma_kernel(float* __restrict__ out) {
    const int ty = blockIdx.y;
    int e = -1, tt = 0, cnt = 0;
    {
        int n = 0;
        #pragma unroll
        for (int i = 0; i < NUM_EXPERT; i++) {
            int ci = g_counts[i];
            int nti = (ci + BM - 1) >> 7;
            if (e < 0 && ty < n + nti) { e = i; tt = ty - n; cnt = ci; }
            n += nti;
        }
    }
    if (e < 0) return;
    const int row0 = tt * BM;
    const int col0 = blockIdx.x * BN;

    extern __shared__ char smem[];
    int* srows = (int*)smem;

    const int tid = threadIdx.x;
    const int wid = tid >> 5;
    const int lane = tid & 31;
    const int warp_m = wid >> 2;      // 0..1 -> 64-row half
    const int warp_n = wid & 3;       // 0..3 -> 32-col quarter

    if (tid < BM) {
        int r = row0 + tid;
        srows[tid] = (r < cnt) ? g_rows[e * BATCH + r] : -1;
    }
    __syncthreads();

    const uint32_t TILES = smem_u32(smem) + SMEM_TILES;

    // ---- A cp.async: 4 x 16B per thread per chunk (128 rows x 128B)
    const unsigned short* a_p[4];
    uint32_t a_dst[4], abytes[4];
    #pragma unroll
    for (int i = 0; i < 4; i++) {
        int idx = tid + i * THREADS;   // 0..1023
        int m  = idx >> 3;
        int kq = idx & 7;
        a_dst[i] = (uint32_t)(m * ROWB + kq * 16);
        int r = srows[m];
        abytes[i] = (r >= 0) ? 16u : 0u;
        a_p[i] = g_ahi + ((size_t)(r < 0 ? 0 : r) << 10) + kq * 8;
    }

    // ---- W fragment pointer (half-chunk = 32k granularity, as in g_wf layout)
    const uint4* wq = g_wf +
        ((size_t)((e * 32 + blockIdx.x * 4 + warp_n) * 32)) * 128 + lane;

    // ---- A ldsm per-lane offset
    const uint32_t a_off =
        (uint32_t)((warp_m * 64 + (lane & 15)) * SPAD + ((lane >> 4) << 3)) * 2;

    float acc[4][4][4];
    #pragma unroll
    for (int mt = 0; mt < 4; mt++)
        #pragma unroll
        for (int nt = 0; nt < 4; nt++)
            #pragma unroll
            for (int q = 0; q < 4; q++) acc[mt][nt][q] = 0.0f;

    // ---- prologue: A stages 0..NSTAGE-2, W half 0
    #pragma unroll
    for (int s = 0; s < NSTAGE - 1; s++) {
        uint32_t base = TILES + s * ASTAGE;
        #pragma unroll
        for (int i = 0; i < 4; i++)
            cp16(base + a_dst[i], a_p[i] + s * BK, abytes[i]);
        cp_commit();
    }
    uint32_t wbuf[2][16];
    #pragma unroll
    for (int j = 0; j < 4; j++) {
        uint4 t = __ldg(wq + j * 32);
        wbuf[0][j * 4 + 0] = t.x; wbuf[0][j * 4 + 1] = t.y;
        wbuf[0][j * 4 + 2] = t.z; wbuf[0][j * 4 + 3] = t.w;
    }

    #pragma unroll 1
    for (int c = 0; c < NCHUNK; c++) {
        cp_wait<NSTAGE - 2>();      // A chunk c landed
        __syncthreads();

        const int cn = c + NSTAGE - 1;
        if (cn < NCHUNK) {
            uint32_t base = TILES + (uint32_t)(cn % NSTAGE) * ASTAGE;
            #pragma unroll
            for (int i = 0; i < 4; i++)
                cp16(base + a_dst[i], a_p[i] + cn * BK, abytes[i]);
        }
        cp_commit();

        const uint32_t soff = TILES + (uint32_t)(c % NSTAGE) * ASTAGE;

        // ---- half 0: prefetch W half (2c+1) into wbuf[1], compute wbuf[0]
        #pragma unroll
        for (int j = 0; j < 4; j++) {
            uint4 t = __ldg(wq + (size_t)(2 * c + 1) * 128 + j * 32);
            wbuf[1][j * 4 + 0] = t.x; wbuf[1][j * 4 + 1] = t.y;
            wbuf[1][j * 4 + 2] = t.z; wbuf[1][j * 4 + 3] = t.w;
        }
        #pragma unroll
        for (int ks = 0; ks < 2; ks++) {
            #pragma unroll
            for (int mt = 0; mt < 4; mt++) {
                uint32_t a_[4];
                ldsm4(a_, soff + a_off + ks * 32 + mt * (16 * ROWB));
                #pragma unroll
                for (int nt = 0; nt < 4; nt++)
                    mma16816(acc[mt][nt], a_,
                             &wbuf[0][(ks * 2 + (nt >> 1)) * 4 + (nt & 1) * 2]);
            }
        }

        // ---- half 1: prefetch W half (2c+2) into wbuf[0], compute wbuf[1]
        if (c + 1 < NCHUNK) {
            #pragma unroll
            for (int j = 0; j < 4; j++) {
                uint4 t = __ldg(wq + (size_t)(2 * c + 2) * 128 + j * 32);
                wbuf[0][j * 4 + 0] = t.x; wbuf[0][j * 4 + 1] = t.y;
                wbuf[0][j * 4 + 2] = t.z; wbuf[0][j * 4 + 3] = t.w;
            }
        }
        #pragma unroll
        for (int ks = 0; ks < 2; ks++) {
            #pragma unroll
            for (int mt = 0; mt < 4; mt++) {
                uint32_t a_[4];
                ldsm4(a_, soff + a_off + 64 + ks * 32 + mt * (16 * ROWB));
                #pragma unroll
                for (int nt = 0; nt < 4; nt++)
                    mma16816(acc[mt][nt], a_,
                             &wbuf[1][(ks * 2 + (nt >> 1)) * 4 + (nt & 1) * 2]);
            }
        }
    }

    // ---- epilogue
    const int rbase = warp_m * 64 + (lane >> 2);
    const int cbase = col0 + warp_n * 32 + (lane & 3) * 2;
    #pragma unroll
    for (int mt = 0; mt < 4; mt++) {
        int r0 = srows[rbase + mt * 16];
        int r1 = srows[rbase + mt * 16 + 8];
        #pragma unroll
        for (int nt = 0; nt < 4; nt++) {
            int col = cbase + nt * 8;
            if (r0 >= 0)
                *reinterpret_cast<float2*>(out + (size_t)r0 * OUT_FEAT + col) =
                    make_float2(acc[mt][nt][0], acc[mt][nt][1]);
            if (r1 >= 0)
                *reinterpret_cast<float2*>(out + (size_t)r1 * OUT_FEAT + col) =
                    make_float2(acc[mt][nt][2], acc[mt][nt][3]);
        }
    }
}

extern "C" void kernel_launch(void* const* d_in, const int* in_sizes, int n_in,
                              void* d_out, int out_size) {
    const float* inp    = (const float*)d_in[0];   // [8192, 1024] f32
    const int*   gate   = (const int*)d_in[1];     // [8192] i32
    const float* weight = (const float*)d_in[2];   // [16, 1024, 1024] f32
    float* out = (float*)d_out;                    // [8192, 1024] f32

    cudaFuncSetAttribute(moe_mma_kernel, cudaFuncAttributeMaxDynamicSharedMemorySize,
                         SMEM_TOTAL);

    void* counts_ptr = nullptr;
    cudaGetSymbolAddress(&counts_ptr, g_counts);
    cudaMemsetAsync(counts_ptr, 0, NUM_EXPERT * sizeof(int));

    convert_all_kernel<<<WBLOCKS + ABLOCKS, 256>>>(weight, inp, gate);

    dim3 grid(OUT_FEAT / BN, MAX_TILES, 1);
    moe_mma_kernel<<<grid, THREADS, SMEM_TOTAL>>>(out);
}

// round 13
// speedup vs baseline: 1.3937x; 1.0450x over previous
#include <cuda_runtime.h>
#include <cuda_fp16.h>
#include <cstdint>

#define NUM_EXPERT 16
#define IN_FEAT 1024
#define OUT_FEAT 1024
#define BATCH 8192

#define BM 128
#define BN 128
#define BK 128
#define NCHUNK (IN_FEAT / BK)    // 8
#define THREADS 256
#define SPAD 136                 // fp16 per A smem row (128 data + 8 pad)
#define ROWB (SPAD * 2)          // 272 B
#define ASTAGE (BM * ROWB)       // 34816
#define NSTAGE 2
#define SMEM_TILES 512
#define SMEM_TOTAL (SMEM_TILES + NSTAGE * ASTAGE)   // 70144

#define MAX_TILES 79
#define WBLOCKS (NUM_EXPERT * OUT_FEAT * IN_FEAT / 2 / 4 / 256)  // 8192
#define ABLOCKS (BATCH * IN_FEAT / 8 / 256)                      // 1024

__device__ int g_counts[NUM_EXPERT];
__device__ int g_rows[NUM_EXPERT * BATCH];
// W in HMMA B-fragment layout: [e][ntile(32)][half32k(32)][j(4)][lane(32)] uint4
__device__ uint4 g_wf[NUM_EXPERT * 32 * 32 * 128];               // 33.5 MB
__device__ __align__(16) unsigned short g_ahi[BATCH * IN_FEAT];  // 16.8 MB

// ---------------- helpers ----------------
__device__ __forceinline__ uint32_t smem_u32(const void* p) {
    uint32_t a;
    asm("{ .reg .u64 t; cvta.to.shared.u64 t, %1; cvt.u32.u64 %0, t; }" : "=r"(a) : "l"(p));
    return a;
}
__device__ __forceinline__ uint32_t pack_h2(float x, float y) {
    uint32_t r;
    asm("cvt.rn.f16x2.f32 %0, %1, %2;" : "=r"(r) : "f"(y), "f"(x));
    return r;
}
__device__ __forceinline__ void cp16(uint32_t dst, const void* src, uint32_t bytes) {
    asm volatile("cp.async.cg.shared.global [%0], [%1], 16, %2;"
                 :: "r"(dst), "l"(src), "r"(bytes) : "memory");
}
__device__ __forceinline__ void cp_commit() {
    asm volatile("cp.async.commit_group;" ::: "memory");
}
template <int N>
__device__ __forceinline__ void cp_wait() {
    asm volatile("cp.async.wait_group %0;" :: "n"(N) : "memory");
}
__device__ __forceinline__ void ldsm4(uint32_t* r, uint32_t addr) {
    asm volatile("ldmatrix.sync.aligned.m8n8.x4.shared.b16 {%0,%1,%2,%3}, [%4];"
                 : "=r"(r[0]), "=r"(r[1]), "=r"(r[2]), "=r"(r[3]) : "r"(addr));
}
__device__ __forceinline__ void mma16816(float* d, const uint32_t* a, const uint32_t* b) {
    asm volatile(
        "mma.sync.aligned.m16n8k16.row.col.f32.f16.f16.f32 "
        "{%0,%1,%2,%3}, {%4,%5,%6,%7}, {%8,%9}, {%0,%1,%2,%3};"
        : "+f"(d[0]), "+f"(d[1]), "+f"(d[2]), "+f"(d[3])
        : "r"(a[0]), "r"(a[1]), "r"(a[2]), "r"(a[3]), "r"(b[0]), "r"(b[1]));
}

// ---------------- fused prepass: W permute + A convert + routing ----------------
__global__ __launch_bounds__(256)
void convert_all_kernel(const float* __restrict__ w,
                        const float* __restrict__ a,
                        const int* __restrict__ gate) {
    if (blockIdx.x < WBLOCKS) {
        int t = blockIdx.x * 256 + threadIdx.x;
        int l = t & 31, j = (t >> 5) & 3, c = (t >> 7) & 31;
        int nt = (t >> 12) & 31, e = t >> 17;
        int ks = j >> 1;
        int kbase = c * 32 + ks * 16 + (l & 3) * 2;
        uint4 d;
        uint32_t* dq = (uint32_t*)&d;
        #pragma unroll
        for (int q = 0; q < 4; q++) {
            int n = nt * 32 + ((j & 1) * 2 + (q >> 1)) * 8 + (l >> 2);
            int k = kbase + (q & 1) * 8;
            float2 v = *reinterpret_cast<const float2*>(
                w + (((size_t)e << 10) + n) * IN_FEAT + k);
            dq[q] = pack_h2(v.x, v.y);
        }
        g_wf[t] = d;
    } else {
        int b = blockIdx.x - WBLOCKS;
        int jj = b * 256 + threadIdx.x;
        if (jj < BATCH) {
            int e = gate[jj];
            int pos = atomicAdd(&g_counts[e], 1);
            g_rows[e * BATCH + pos] = jj;
        }
        int i = jj * 2;
        #pragma unroll
        for (int q = 0; q < 2; q++) {
            float4 v = reinterpret_cast<const float4*>(a)[i + q];
            reinterpret_cast<uint2*>(g_ahi)[i + q] =
                make_uint2(pack_h2(v.x, v.y), pack_h2(v.z, v.w));
        }
    }
}

// ---------------- grouped GEMM: BK=128, 2-stage A, W-frag LDG double-buffer --------
__global__ __launch_bounds__(THREADS, 2)
void moe_mma_kernel(float* __restrict__ out) {
    const int ty = blockIdx.y;
    int e = -1, tt = 0, cnt = 0;
    {
        int n = 0;
        #pragma unroll
        for (int i = 0; i < NUM_EXPERT; i++) {
            int ci = g_counts[i];
            int nti = (ci + BM - 1) >> 7;
            if (e < 0 && ty < n + nti) { e = i; tt = ty - n; cnt = ci; }
            n += nti;
        }
    }
    if (e < 0) return;
    const int row0 = tt * BM;
    const int col0 = blockIdx.x * BN;

    extern __shared__ char smem[];
    int* srows = (int*)smem;

    const int tid = threadIdx.x;
    const int wid = tid >> 5;
    const int lane = tid & 31;
    const int warp_m = wid >> 2;      // 0..1 -> 64-row half
    const int warp_n = wid & 3;       // 0..3 -> 32-col quarter

    if (tid < BM) {
        int r = row0 + tid;
        srows[tid] = (r < cnt) ? g_rows[e * BATCH + r] : -1;
    }
    __syncthreads();

    const uint32_t TILES = smem_u32(smem) + SMEM_TILES;

    // ---- A cp.async geometry: 8 x 16B per thread per chunk (128 rows x 256B)
    //      kq = tid & 15 constant across i; rows m = m0 + 16*i
    const int m0 = tid >> 4;
    const int kq = tid & 15;
    const uint32_t a_dst0 = (uint32_t)(m0 * ROWB + kq * 16);
    const unsigned short* a_base = g_ahi + kq * 8;

    // ---- W fragment pointer (32k-half granularity)
    const uint4* wq = g_wf +
        ((size_t)((e * 32 + blockIdx.x * 4 + warp_n) * 32)) * 128 + lane;

    // ---- A ldsm per-lane offset
    const uint32_t a_off =
        (uint32_t)((warp_m * 64 + (lane & 15)) * SPAD + ((lane >> 4) << 3)) * 2;

    float acc[4][4][4];
    #pragma unroll
    for (int mt = 0; mt < 4; mt++)
        #pragma unroll
        for (int nt = 0; nt < 4; nt++)
            #pragma unroll
            for (int q = 0; q < 4; q++) acc[mt][nt][q] = 0.0f;

    // ---- prologue: A chunk 0 into stage 0, W half 0 into wbuf[0]
    #pragma unroll
    for (int i = 0; i < 8; i++) {
        int r = srows[m0 + 16 * i];
        cp16(TILES + a_dst0 + (uint32_t)i * (16 * ROWB),
             a_base + ((size_t)(r < 0 ? 0 : r) << 10), (r >= 0) ? 16u : 0u);
    }
    cp_commit();

    uint32_t wbuf[2][16];
    #pragma unroll
    for (int j = 0; j < 4; j++) {
        uint4 t = __ldg(wq + j * 32);
        wbuf[0][j * 4 + 0] = t.x; wbuf[0][j * 4 + 1] = t.y;
        wbuf[0][j * 4 + 2] = t.z; wbuf[0][j * 4 + 3] = t.w;
    }

    #pragma unroll 1
    for (int c = 0; c < NCHUNK; c++) {
        cp_wait<0>();               // A chunk c landed
        __syncthreads();            // all warps done reading stage (c-1)

        // issue A chunk c+1 into the other stage
        if (c + 1 < NCHUNK) {
            uint32_t base = TILES + (uint32_t)((c + 1) & 1) * ASTAGE;
            const unsigned short* ap = a_base + (c + 1) * BK;
            #pragma unroll
            for (int i = 0; i < 8; i++) {
                int r = srows[m0 + 16 * i];
                cp16(base + a_dst0 + (uint32_t)i * (16 * ROWB),
                     ap + ((size_t)(r < 0 ? 0 : r) << 10), (r >= 0) ? 16u : 0u);
            }
        }
        cp_commit();

        const uint32_t soff = TILES + (uint32_t)(c & 1) * ASTAGE;

        // 4 W-halves per chunk; prefetch h+1 while computing h
        #pragma unroll
        for (int h = 0; h < 4; h++) {
            const int g = 4 * c + h;
            if (g + 1 < 32) {
                #pragma unroll
                for (int j = 0; j < 4; j++) {
                    uint4 t = __ldg(wq + (size_t)(g + 1) * 128 + j * 32);
                    wbuf[(h + 1) & 1][j * 4 + 0] = t.x;
                    wbuf[(h + 1) & 1][j * 4 + 1] = t.y;
                    wbuf[(h + 1) & 1][j * 4 + 2] = t.z;
                    wbuf[(h + 1) & 1][j * 4 + 3] = t.w;
                }
            }
            #pragma unroll
            for (int ks = 0; ks < 2; ks++) {
                #pragma unroll
                for (int mt = 0; mt < 4; mt++) {
                    uint32_t a_[4];
                    ldsm4(a_, soff + a_off + h * 64 + ks * 32 + mt * (16 * ROWB));
                    #pragma unroll
                    for (int nt = 0; nt < 4; nt++)
                        mma16816(acc[mt][nt], a_,
                                 &wbuf[h & 1][(ks * 2 + (nt >> 1)) * 4 + (nt & 1) * 2]);
                }
            }
        }
    }

    // ---- epilogue
    const int rbase = warp_m * 64 + (lane >> 2);
    const int cbase = col0 + warp_n * 32 + (lane & 3) * 2;
    #pragma unroll
    for (int mt = 0; mt < 4; mt++) {
        int r0 = srows[rbase + mt * 16];
        int r1 = srows[rbase + mt * 16 + 8];
        #pragma unroll
        for (int nt = 0; nt < 4; nt++) {
            int col = cbase + nt * 8;
            if (r0 >= 0)
                *reinterpret_cast<float2*>(out + (size_t)r0 * OUT_FEAT + col) =
                    make_float2(acc[mt][nt][0], acc[mt][nt][1]);
            if (r1 >= 0)
                *reinterpret_cast<float2*>(out + (size_t)r1 * OUT_FEAT + col) =
                    make_float2(acc[mt][nt][2], acc[mt][nt][3]);
        }
    }
}

extern "C" void kernel_launch(void* const* d_in, const int* in_sizes, int n_in,
                              void* d_out, int out_size) {
    const float* inp    = (const float*)d_in[0];   // [8192, 1024] f32
    const int*   gate   = (const int*)d_in[1];     // [8192] i32
    const float* weight = (const float*)d_in[2];   // [16, 1024, 1024] f32
    float* out = (float*)d_out;                    // [8192, 1024] f32

    cudaFuncSetAttribute(moe_mma_kernel, cudaFuncAttributeMaxDynamicSharedMemorySize,
                         SMEM_TOTAL);

    void* counts_ptr = nullptr;
    cudaGetSymbolAddress(&counts_ptr, g_counts);
    cudaMemsetAsync(counts_ptr, 0, NUM_EXPERT * sizeof(int));

    convert_all_kernel<<<WBLOCKS + ABLOCKS, 256>>>(weight, inp, gate);

    dim3 grid(OUT_FEAT / BN, MAX_TILES, 1);
    moe_mma_kernel<<<grid, THREADS, SMEM_TOTAL>>>(out);
}